// round 5
// baseline (speedup 1.0000x reference)
#include <cuda_runtime.h>
#include <cuda_bf16.h>
#include <mma.h>
#include <cstdint>

using namespace nvcuda;

// Problem dims (fixed by the reference)
#define NE 8
#define NT 1024
#define ND 2048
#define NI 4096

// Intermediate H = silu(x@gp) * (x@ip), per expert [T, I] fp32. 128 MB scratch.
__device__ float g_H[(size_t)NE * NT * NI];

// Tiling
constexpr int BM = 128;   // rows (tokens) per block
constexpr int BN = 64;    // cols per block
constexpr int BK = 32;    // k per mainloop step (4 mma k-steps of 8)
constexpr int WM = 32;    // per-warp tile rows
constexpr int WN = 32;    // per-warp tile cols
constexpr int WARPS_M = BM / WM;   // 4
constexpr int WARPS_N = BN / WN;   // 2
constexpr int NTHR = 32 * WARPS_M * WARPS_N;  // 256

constexpr int APAD = 4;   // smem padding (keeps 16B row alignment, ld % 4 == 0)
constexpr int BPAD = 4;

// ---------------------------------------------------------------------------
// Kernel 1: fused dual GEMM + GLU.
//   For expert e, block computes a 128x64 tile of both
//     G = x @ gate_w   and   U = x @ inner_w,
//   then writes H = silu(G) * U to g_H.
//   x:       [E, T, D] row-major (ld = D)
//   gate_w:  [E*D, I]  row-major -> per-expert [D, I] (ld = I)
//   inner_w: [E*D, I]  row-major -> per-expert [D, I] (ld = I)
// ---------------------------------------------------------------------------
__global__ __launch_bounds__(NTHR, 1)
void glu_gemm_kernel(const float* __restrict__ x,
                     const float* __restrict__ gate_w,
                     const float* __restrict__ inner_w)
{
    const int e      = blockIdx.z;
    const int rowBlk = blockIdx.y;   // 0..T/BM-1
    const int colBlk = blockIdx.x;   // 0..I/BN-1

    __shared__ float As[BM][BK + APAD];
    __shared__ float Bg[BK][BN + BPAD];
    __shared__ float Bu[BK][BN + BPAD];

    const float* xA = x + ((size_t)e * NT + (size_t)rowBlk * BM) * ND;
    const float* gW = gate_w  + (size_t)e * ND * NI + (size_t)colBlk * BN;
    const float* iW = inner_w + (size_t)e * ND * NI + (size_t)colBlk * BN;

    const int tid  = threadIdx.x;
    const int warp = tid >> 5;
    const int wm   = warp % WARPS_M;
    const int wn   = warp / WARPS_M;

    wmma::fragment<wmma::accumulator, 16, 16, 8, float> accG[2][2], accU[2][2];
    #pragma unroll
    for (int i = 0; i < 2; i++)
        #pragma unroll
        for (int j = 0; j < 2; j++) {
            wmma::fill_fragment(accG[i][j], 0.0f);
            wmma::fill_fragment(accU[i][j], 0.0f);
        }

    for (int k0 = 0; k0 < ND; k0 += BK) {
        // --- fill A tile: 128 x 32 floats = 1024 float4, 4 per thread ---
        #pragma unroll
        for (int it = 0; it < 4; it++) {
            int f = tid + it * NTHR;          // 0..1023
            int r = f >> 3;                   // row 0..127
            int c = (f & 7) << 2;             // col 0,4,...,28
            float4 v = *reinterpret_cast<const float4*>(xA + (size_t)r * ND + k0 + c);
            As[r][c + 0] = v.x; As[r][c + 1] = v.y;
            As[r][c + 2] = v.z; As[r][c + 3] = v.w;
        }
        // --- fill Bg/Bu tiles: 32 x 64 floats = 512 float4 each, 2 per thread ---
        #pragma unroll
        for (int it = 0; it < 2; it++) {
            int f = tid + it * NTHR;          // 0..511
            int r = f >> 4;                   // k-row 0..31
            int c = (f & 15) << 2;            // col 0,4,...,60
            float4 vg = *reinterpret_cast<const float4*>(gW + (size_t)(k0 + r) * NI + c);
            Bg[r][c + 0] = vg.x; Bg[r][c + 1] = vg.y;
            Bg[r][c + 2] = vg.z; Bg[r][c + 3] = vg.w;
            float4 vu = *reinterpret_cast<const float4*>(iW + (size_t)(k0 + r) * NI + c);
            Bu[r][c + 0] = vu.x; Bu[r][c + 1] = vu.y;
            Bu[r][c + 2] = vu.z; Bu[r][c + 3] = vu.w;
        }
        __syncthreads();

        #pragma unroll
        for (int kk = 0; kk < BK / 8; kk++) {
            wmma::fragment<wmma::matrix_a, 16, 16, 8, wmma::precision::tf32, wmma::row_major> a[2];
            wmma::fragment<wmma::matrix_b, 16, 16, 8, wmma::precision::tf32, wmma::row_major> bg[2], bu[2];
            #pragma unroll
            for (int i = 0; i < 2; i++) {
                wmma::load_matrix_sync(a[i], &As[wm * WM + i * 16][kk * 8], BK + APAD);
                #pragma unroll
                for (int t = 0; t < a[i].num_elements; t++)
                    a[i].x[t] = wmma::__float_to_tf32(a[i].x[t]);
            }
            #pragma unroll
            for (int j = 0; j < 2; j++) {
                wmma::load_matrix_sync(bg[j], &Bg[kk * 8][wn * WN + j * 16], BN + BPAD);
                wmma::load_matrix_sync(bu[j], &Bu[kk * 8][wn * WN + j * 16], BN + BPAD);
                #pragma unroll
                for (int t = 0; t < bg[j].num_elements; t++) {
                    bg[j].x[t] = wmma::__float_to_tf32(bg[j].x[t]);
                    bu[j].x[t] = wmma::__float_to_tf32(bu[j].x[t]);
                }
            }
            #pragma unroll
            for (int i = 0; i < 2; i++)
                #pragma unroll
                for (int j = 0; j < 2; j++) {
                    wmma::mma_sync(accG[i][j], a[i], bg[j], accG[i][j]);
                    wmma::mma_sync(accU[i][j], a[i], bu[j], accU[i][j]);
                }
        }
        __syncthreads();
    }

    // Epilogue: H = silu(G) * U in-register (G/U accumulator layouts match),
    // then store row-major to g_H.
    float* Hout = g_H + ((size_t)e * NT + (size_t)rowBlk * BM) * NI
                      + (size_t)colBlk * BN;
    #pragma unroll
    for (int i = 0; i < 2; i++)
        #pragma unroll
        for (int j = 0; j < 2; j++) {
            #pragma unroll
            for (int t = 0; t < accG[i][j].num_elements; t++) {
                float g = accG[i][j].x[t];
                float u = accU[i][j].x[t];
                accG[i][j].x[t] = (g / (1.0f + __expf(-g))) * u;
            }
            wmma::store_matrix_sync(
                Hout + (size_t)(wm * WM + i * 16) * NI + wn * WN + j * 16,
                accG[i][j], NI, wmma::mem_row_major);
        }
}

// ---------------------------------------------------------------------------
// Kernel 2: out = H @ op  per expert.
//   H:  [E, T, I] row-major (ld = I)  (g_H scratch)
//   op: [E*I, D]  row-major -> per-expert [I, D] (ld = D)
//   out:[E, T, D] row-major (ld = D)
// ---------------------------------------------------------------------------
__global__ __launch_bounds__(NTHR, 1)
void out_gemm_kernel(const float* __restrict__ out_w,
                     float* __restrict__ out)
{
    const int e      = blockIdx.z;
    const int rowBlk = blockIdx.y;   // 0..T/BM-1
    const int colBlk = blockIdx.x;   // 0..D/BN-1

    __shared__ float As[BM][BK + APAD];
    __shared__ float Bs[BK][BN + BPAD];

    const float* hA = g_H + ((size_t)e * NT + (size_t)rowBlk * BM) * NI;
    const float* oW = out_w + (size_t)e * NI * ND + (size_t)colBlk * BN;

    const int tid  = threadIdx.x;
    const int warp = tid >> 5;
    const int wm   = warp % WARPS_M;
    const int wn   = warp / WARPS_M;

    wmma::fragment<wmma::accumulator, 16, 16, 8, float> acc[2][2];
    #pragma unroll
    for (int i = 0; i < 2; i++)
        #pragma unroll
        for (int j = 0; j < 2; j++)
            wmma::fill_fragment(acc[i][j], 0.0f);

    for (int k0 = 0; k0 < NI; k0 += BK) {
        #pragma unroll
        for (int it = 0; it < 4; it++) {
            int f = tid + it * NTHR;
            int r = f >> 3;
            int c = (f & 7) << 2;
            float4 v = *reinterpret_cast<const float4*>(hA + (size_t)r * NI + k0 + c);
            As[r][c + 0] = v.x; As[r][c + 1] = v.y;
            As[r][c + 2] = v.z; As[r][c + 3] = v.w;
        }
        #pragma unroll
        for (int it = 0; it < 2; it++) {
            int f = tid + it * NTHR;
            int r = f >> 4;
            int c = (f & 15) << 2;
            float4 v = *reinterpret_cast<const float4*>(oW + (size_t)(k0 + r) * ND + c);
            Bs[r][c + 0] = v.x; Bs[r][c + 1] = v.y;
            Bs[r][c + 2] = v.z; Bs[r][c + 3] = v.w;
        }
        __syncthreads();

        #pragma unroll
        for (int kk = 0; kk < BK / 8; kk++) {
            wmma::fragment<wmma::matrix_a, 16, 16, 8, wmma::precision::tf32, wmma::row_major> a[2];
            wmma::fragment<wmma::matrix_b, 16, 16, 8, wmma::precision::tf32, wmma::row_major> b[2];
            #pragma unroll
            for (int i = 0; i < 2; i++) {
                wmma::load_matrix_sync(a[i], &As[wm * WM + i * 16][kk * 8], BK + APAD);
                #pragma unroll
                for (int t = 0; t < a[i].num_elements; t++)
                    a[i].x[t] = wmma::__float_to_tf32(a[i].x[t]);
            }
            #pragma unroll
            for (int j = 0; j < 2; j++) {
                wmma::load_matrix_sync(b[j], &Bs[kk * 8][wn * WN + j * 16], BN + BPAD);
                #pragma unroll
                for (int t = 0; t < b[j].num_elements; t++)
                    b[j].x[t] = wmma::__float_to_tf32(b[j].x[t]);
            }
            #pragma unroll
            for (int i = 0; i < 2; i++)
                #pragma unroll
                for (int j = 0; j < 2; j++)
                    wmma::mma_sync(acc[i][j], a[i], b[j], acc[i][j]);
        }
        __syncthreads();
    }

    float* Oout = out + ((size_t)e * NT + (size_t)rowBlk * BM) * ND
                      + (size_t)colBlk * BN;
    #pragma unroll
    for (int i = 0; i < 2; i++)
        #pragma unroll
        for (int j = 0; j < 2; j++)
            wmma::store_matrix_sync(
                Oout + (size_t)(wm * WM + i * 16) * ND + wn * WN + j * 16,
                acc[i][j], ND, wmma::mem_row_major);
}

// ---------------------------------------------------------------------------
// Harness entry. Inputs (metadata order): x, gate_proj, inner_proj, output_proj.
// All fp32. Output fp32 [E, T, D]. Graph-capturable: two kernel launches only.
// ---------------------------------------------------------------------------
extern "C" void kernel_launch(void* const* d_in, const int* in_sizes, int n_in,
                              void* d_out, int out_size)
{
    const float* x       = (const float*)d_in[0];
    const float* gate_w  = (const float*)d_in[1];
    const float* inner_w = (const float*)d_in[2];
    const float* out_w   = (const float*)d_in[3];
    float* out = (float*)d_out;

    {
        dim3 grid(NI / BN, NT / BM, NE);   // (64, 8, 8) = 4096 blocks
        glu_gemm_kernel<<<grid, NTHR>>>(x, gate_w, inner_w);
    }
    {
        dim3 grid(ND / BN, NT / BM, NE);   // (32, 8, 8) = 2048 blocks
        out_gemm_kernel<<<grid, NTHR>>>(out_w, out);
    }
}

// round 7
// speedup vs baseline: 6.7189x; 6.7189x over previous
#include <cuda_runtime.h>
#include <cuda_fp16.h>
#include <cstdint>

// Problem dims (fixed by the reference)
#define NE 8
#define NT 1024
#define ND 2048
#define NI 4096

// ---------------------------------------------------------------------------
// __device__ scratch (alloc-free rule): fp16 copies of inputs + intermediate H
// ---------------------------------------------------------------------------
__device__ __half g_xh [(size_t)NE * NT * ND];   //  32 MB
__device__ __half g_gwh[(size_t)NE * ND * NI];   // 134 MB
__device__ __half g_iwh[(size_t)NE * ND * NI];   // 134 MB
__device__ __half g_owh[(size_t)NE * NI * ND];   // 134 MB
__device__ __half g_H  [(size_t)NE * NT * NI];   //  67 MB

// ---------------------------------------------------------------------------
// PTX helpers (baseline sm_80+ instructions only — compute_103-safe)
// ---------------------------------------------------------------------------
__device__ __forceinline__ uint32_t smem_u32(const void* p) {
    uint32_t a;
    asm("{ .reg .u64 t; cvta.to.shared.u64 t, %1; cvt.u32.u64 %0, t; }"
        : "=r"(a) : "l"(p));
    return a;
}
__device__ __forceinline__ void cp16(uint32_t saddr, const void* g) {
    asm volatile("cp.async.cg.shared.global [%0], [%1], 16;"
                 :: "r"(saddr), "l"(g) : "memory");
}
__device__ __forceinline__ void cp_commit() {
    asm volatile("cp.async.commit_group;" ::: "memory");
}
template <int N> __device__ __forceinline__ void cp_wait() {
    asm volatile("cp.async.wait_group %0;" :: "n"(N) : "memory");
}
__device__ __forceinline__ void ldsm4(uint32_t* r, uint32_t a) {
    asm volatile("ldmatrix.sync.aligned.m8n8.x4.shared.b16 {%0,%1,%2,%3}, [%4];"
                 : "=r"(r[0]), "=r"(r[1]), "=r"(r[2]), "=r"(r[3]) : "r"(a));
}
__device__ __forceinline__ void ldsm4t(uint32_t* r, uint32_t a) {
    asm volatile("ldmatrix.sync.aligned.m8n8.x4.trans.shared.b16 {%0,%1,%2,%3}, [%4];"
                 : "=r"(r[0]), "=r"(r[1]), "=r"(r[2]), "=r"(r[3]) : "r"(a));
}
__device__ __forceinline__ void mma16816(float* c, const uint32_t* a,
                                         uint32_t b0, uint32_t b1) {
    asm volatile(
        "mma.sync.aligned.m16n8k16.row.col.f32.f16.f16.f32 "
        "{%0,%1,%2,%3}, {%4,%5,%6,%7}, {%8,%9}, {%0,%1,%2,%3};"
        : "+f"(c[0]), "+f"(c[1]), "+f"(c[2]), "+f"(c[3])
        : "r"(a[0]), "r"(a[1]), "r"(a[2]), "r"(a[3]), "r"(b0), "r"(b1));
}
#define SWZ(b) ((b) ^ (((b) >> 3) & 0x70))   // SW128: conflict-free ldmatrix

// ---------------------------------------------------------------------------
// Kernel 0: fp32 -> fp16 conversion (grid-stride, vectorized)
// ---------------------------------------------------------------------------
__global__ void cvt_f2h(const float* __restrict__ s, __half* __restrict__ d,
                        size_t n)
{
    size_t i = ((size_t)blockIdx.x * blockDim.x + threadIdx.x) * 4;
    size_t stride = (size_t)gridDim.x * blockDim.x * 4;
    for (; i < n; i += stride) {
        float4 v = *(const float4*)(s + i);
        __half2* o = (__half2*)(d + i);
        o[0] = __floats2half2_rn(v.x, v.y);
        o[1] = __floats2half2_rn(v.z, v.w);
    }
}

// ===========================================================================
// Kernel 1: fused dual GEMM + GLU.
//   G = x@gp, U = x@ip (both 128x64 tiles, shared A), H = silu(G)*U -> g_H.
//   Tiles: BM=128, BN=64, BK=64, 3-stage cp.async pipeline, 8 warps (4x2).
//   smem/stage: A 16KB + Bg 8KB + Bu 8KB = 32KB; total 96KB.
// ===========================================================================
__global__ __launch_bounds__(256)
void glu_mma_kernel()
{
    extern __shared__ char smem[];
    const uint32_t sb = smem_u32(smem);
    const int tid = threadIdx.x, warp = tid >> 5, lane = tid & 31;
    const int wm = warp & 3, wn = warp >> 2;
    const int m0 = blockIdx.x * 128, n0 = blockIdx.y * 64, e = blockIdx.z;

    const __half* Ab = g_xh  + ((size_t)e * NT + m0) * ND;
    const __half* Gb = g_gwh + ((size_t)e * ND) * NI + n0;
    const __half* Ub = g_iwh + ((size_t)e * ND) * NI + n0;

    // per-thread ldmatrix byte offsets (pre-swizzle)
    int aoff[2], boff[2];
    #pragma unroll
    for (int i = 0; i < 2; i++)
        aoff[i] = (wm * 32 + i * 16 + (lane & 15)) * 128 + (lane >> 4) * 16;
    #pragma unroll
    for (int j = 0; j < 2; j++)
        boff[j] = (lane & 15) * 128 + (wn * 32 + j * 16 + (lane >> 4) * 8) * 2;

    float accG[2][4][4] = {}, accU[2][4][4] = {};

    auto load_stage = [&](int kt, int s) {
        const uint32_t sbase = sb + s * 32768;
        const int k0 = kt * 64;
        #pragma unroll
        for (int i = 0; i < 4; i++) {            // A: 128x64 halves
            int f = tid + i * 256, r = f >> 3, c = (f & 7) * 8;
            cp16(sbase + SWZ(r * 128 + c * 2), Ab + (size_t)r * ND + k0 + c);
        }
        #pragma unroll
        for (int i = 0; i < 2; i++) {            // Bg/Bu: 64x64 halves each
            int f = tid + i * 256, r = f >> 3, c = (f & 7) * 8;
            size_t go = (size_t)(k0 + r) * NI + c;
            cp16(sbase + 16384 + SWZ(r * 128 + c * 2), Gb + go);
            cp16(sbase + 24576 + SWZ(r * 128 + c * 2), Ub + go);
        }
    };

    constexpr int KT = ND / 64;   // 32
    load_stage(0, 0); cp_commit();
    load_stage(1, 1); cp_commit();

    for (int kt = 0; kt < KT; ++kt) {
        cp_wait<1>();
        __syncthreads();
        const int s = kt % 3;
        const uint32_t sA = sb + s * 32768, sBg = sA + 16384, sBu = sA + 24576;
        #pragma unroll
        for (int kk = 0; kk < 4; ++kk) {
            uint32_t a[2][4], bg[2][4], bu[2][4];
            #pragma unroll
            for (int i = 0; i < 2; i++) ldsm4(a[i], sA + SWZ(aoff[i] + kk * 32));
            #pragma unroll
            for (int j = 0; j < 2; j++) {
                ldsm4t(bg[j], sBg + SWZ(boff[j] + kk * 2048));
                ldsm4t(bu[j], sBu + SWZ(boff[j] + kk * 2048));
            }
            #pragma unroll
            for (int i = 0; i < 2; i++)
                #pragma unroll
                for (int j = 0; j < 4; j++) {
                    mma16816(accG[i][j], a[i], bg[j >> 1][(j & 1) * 2],
                             bg[j >> 1][(j & 1) * 2 + 1]);
                    mma16816(accU[i][j], a[i], bu[j >> 1][(j & 1) * 2],
                             bu[j >> 1][(j & 1) * 2 + 1]);
                }
        }
        __syncthreads();
        if (kt + 2 < KT) load_stage(kt + 2, (kt + 2) % 3);
        cp_commit();
    }

    // Epilogue: H = silu(G)*U, fp16 store. c-frag: rows lane>>2 (+8), cols 2*(lane&3).
    __half* Hd = g_H + (size_t)e * NT * NI;
    const int rb = m0 + wm * 32 + (lane >> 2);
    const int cb = n0 + wn * 32 + (lane & 3) * 2;
    #pragma unroll
    for (int i = 0; i < 2; i++)
        #pragma unroll
        for (int j = 0; j < 4; j++) {
            #pragma unroll
            for (int h = 0; h < 2; h++) {   // h=0: row, h=1: row+8
                float g0 = accG[i][j][h * 2],     u0 = accU[i][j][h * 2];
                float g1 = accG[i][j][h * 2 + 1], u1 = accU[i][j][h * 2 + 1];
                float h0 = (g0 / (1.0f + __expf(-g0))) * u0;
                float h1 = (g1 / (1.0f + __expf(-g1))) * u1;
                size_t off = (size_t)(rb + i * 16 + h * 8) * NI + cb + j * 8;
                *(__half2*)(Hd + off) = __floats2half2_rn(h0, h1);
            }
        }
}

// ===========================================================================
// Kernel 2: out = H @ op.  BM=128, BN=128, BK=64, 3 stages, 8 warps (4x2).
//   smem/stage: A 16KB + B 16KB (two 64-col halves) = 32KB; total 96KB.
// ===========================================================================
__global__ __launch_bounds__(256)
void out_mma_kernel(float* __restrict__ out)
{
    extern __shared__ char smem[];
    const uint32_t sb = smem_u32(smem);
    const int tid = threadIdx.x, warp = tid >> 5, lane = tid & 31;
    const int wm = warp & 3, wn = warp >> 2;
    const int m0 = blockIdx.x * 128, n0 = blockIdx.y * 128, e = blockIdx.z;

    const __half* Ab = g_H   + ((size_t)e * NT + m0) * NI;
    const __half* Bb = g_owh + ((size_t)e * NI) * ND + n0;

    int aoff[2];
    #pragma unroll
    for (int i = 0; i < 2; i++)
        aoff[i] = (wm * 32 + i * 16 + (lane & 15)) * 128 + (lane >> 4) * 16;
    // B: [64 k][128 n] stored as two [64][64] halves (128B rows each)
    int bhalf[4], boff[4];
    #pragma unroll
    for (int j = 0; j < 4; j++) {
        int c = wn * 64 + j * 16 + (lane >> 4) * 8;
        bhalf[j] = (c >> 6) * 8192;
        boff[j]  = (lane & 15) * 128 + (c & 63) * 2;
    }

    float acc[2][8][4] = {};

    auto load_stage = [&](int kt, int s) {
        const uint32_t sbase = sb + s * 32768;
        const int k0 = kt * 64;
        #pragma unroll
        for (int i = 0; i < 4; i++) {            // A: 128x64
            int f = tid + i * 256, r = f >> 3, c = (f & 7) * 8;
            cp16(sbase + SWZ(r * 128 + c * 2), Ab + (size_t)r * NI + k0 + c);
        }
        #pragma unroll
        for (int i = 0; i < 4; i++) {            // B: 64x128
            int f = tid + i * 256, r = f >> 4, c = (f & 15) * 8;
            cp16(sbase + 16384 + (c >> 6) * 8192 + SWZ(r * 128 + (c & 63) * 2),
                 Bb + (size_t)(k0 + r) * ND + c);
        }
    };

    constexpr int KT = NI / 64;   // 64
    load_stage(0, 0); cp_commit();
    load_stage(1, 1); cp_commit();

    for (int kt = 0; kt < KT; ++kt) {
        cp_wait<1>();
        __syncthreads();
        const int s = kt % 3;
        const uint32_t sA = sb + s * 32768, sB = sA + 16384;
        #pragma unroll
        for (int kk = 0; kk < 4; ++kk) {
            uint32_t a[2][4], b[4][4];
            #pragma unroll
            for (int i = 0; i < 2; i++) ldsm4(a[i], sA + SWZ(aoff[i] + kk * 32));
            #pragma unroll
            for (int j = 0; j < 4; j++)
                ldsm4t(b[j], sB + bhalf[j] + SWZ(boff[j] + kk * 2048));
            #pragma unroll
            for (int i = 0; i < 2; i++)
                #pragma unroll
                for (int j = 0; j < 8; j++)
                    mma16816(acc[i][j], a[i], b[j >> 1][(j & 1) * 2],
                             b[j >> 1][(j & 1) * 2 + 1]);
        }
        __syncthreads();
        if (kt + 2 < KT) load_stage(kt + 2, (kt + 2) % 3);
        cp_commit();
    }

    // Epilogue: fp32 stores
    float* Od = out + (size_t)e * NT * ND;
    const int rb = m0 + wm * 32 + (lane >> 2);
    const int cb = n0 + wn * 64 + (lane & 3) * 2;
    #pragma unroll
    for (int i = 0; i < 2; i++)
        #pragma unroll
        for (int j = 0; j < 8; j++)
            #pragma unroll
            for (int h = 0; h < 2; h++) {
                size_t off = (size_t)(rb + i * 16 + h * 8) * ND + cb + j * 8;
                float2 v = make_float2(acc[i][j][h * 2], acc[i][j][h * 2 + 1]);
                *(float2*)(Od + off) = v;
            }
}

// ---------------------------------------------------------------------------
// Harness entry. Inputs: x, gate_proj, inner_proj, output_proj (all fp32).
// Sequence: 4 convert kernels -> GEMM1 (GLU) -> GEMM2. All graph-capturable.
// ---------------------------------------------------------------------------
extern "C" void kernel_launch(void* const* d_in, const int* in_sizes, int n_in,
                              void* d_out, int out_size)
{
    const float* x  = (const float*)d_in[0];
    const float* gw = (const float*)d_in[1];
    const float* iw = (const float*)d_in[2];
    const float* ow = (const float*)d_in[3];
    float* out = (float*)d_out;

    __half *xh, *gwh, *iwh, *owh;
    cudaGetSymbolAddress((void**)&xh,  g_xh);
    cudaGetSymbolAddress((void**)&gwh, g_gwh);
    cudaGetSymbolAddress((void**)&iwh, g_iwh);
    cudaGetSymbolAddress((void**)&owh, g_owh);

    const int CB = 1184;   // 8 * 148 blocks
    cvt_f2h<<<CB, 256>>>(x,  xh,  (size_t)NE * NT * ND);
    cvt_f2h<<<CB, 256>>>(gw, gwh, (size_t)NE * ND * NI);
    cvt_f2h<<<CB, 256>>>(iw, iwh, (size_t)NE * ND * NI);
    cvt_f2h<<<CB, 256>>>(ow, owh, (size_t)NE * NI * ND);

    cudaFuncSetAttribute(glu_mma_kernel,
                         cudaFuncAttributeMaxDynamicSharedMemorySize, 98304);
    cudaFuncSetAttribute(out_mma_kernel,
                         cudaFuncAttributeMaxDynamicSharedMemorySize, 98304);

    // grid.x = m-tiles (fastest) so concurrent CTAs share B slabs in L2
    glu_mma_kernel<<<dim3(NT / 128, NI / 64, NE), 256, 98304>>>();
    out_mma_kernel<<<dim3(NT / 128, ND / 128, NE), 256, 98304>>>(out);
}